// round 16
// baseline (speedup 1.0000x reference)
#include <cuda_runtime.h>
#include <cuda_bf16.h>
#include <cstdint>
#include <cstddef>

// Problem constants (fixed by the dataset instance)
#define IN_DIM   128
#define H_E      512     // 2*IN_DIM*SCALE
#define H_S      256     // IN_DIM*SCALE
#define OUT_HALF 128
#define N_TYPES  16
#define MAX_NODES 50000
#define MAX_EDGES 400000

typedef __nv_bfloat16  bf16;
typedef __nv_bfloat162 bf162;

// Scratch (allocation-free rule: __device__ globals)
__device__ bf16  g_Fb [MAX_NODES * H_E];      // F = feat@W1e_bot, single bf16 [N,512]
__device__ bf16  g_Hh [MAX_NODES * H_E];      // H hi  [N,512]
__device__ bf16  g_Hl [MAX_NODES * H_E];      // H lo  [N,512]
__device__ bf16  g_Shh[MAX_NODES * H_S];      // Sh hi [N,256]
__device__ bf16  g_Shl[MAX_NODES * H_S];      // Sh lo [N,256]
__device__ bf16  g_fh [MAX_NODES * IN_DIM];   // features hi [N,128]
__device__ bf16  g_fl [MAX_NODES * IN_DIM];   // features lo [N,128]
// transposed split weights: [n][k]
__device__ bf16  g_W1eh[H_E * IN_DIM],   g_W1el[H_E * IN_DIM];
__device__ bf16  g_W1sh[H_S * IN_DIM],   g_W1sl[H_S * IN_DIM];
__device__ bf16  g_W2eh[OUT_HALF * H_E], g_W2el[OUT_HALF * H_E];
__device__ bf16  g_W2sh[OUT_HALF * H_S], g_W2sl[OUT_HALF * H_S];
__device__ float g_T [N_TYPES * H_E];         // e_emb@W1e_top + b1e  (fp32)
__device__ int   g_deg[MAX_NODES];
__device__ int   g_cnt[MAX_NODES];
__device__ int   g_off[MAX_NODES + 1];
__device__ int   g_cur[MAX_NODES];
__device__ int   g_bsum[256];                 // per-block sums for scan
__device__ int   g_boff[256];                 // per-block exclusive offsets
__device__ int   g_edges[MAX_EDGES];          // packed: src | (type << 20)

// ---------------------------------------------------------------------------
// Conversion kernels (run once per launch, tiny)
// ---------------------------------------------------------------------------
__global__ void split_kernel(const float4* __restrict__ x, uint2* __restrict__ h,
                             uint2* __restrict__ l, int n4)
{
    int i = blockIdx.x * blockDim.x + threadIdx.x;
    if (i >= n4) return;
    float4 v = x[i];
    bf16 h0 = __float2bfloat16(v.x), h1 = __float2bfloat16(v.y);
    bf16 h2 = __float2bfloat16(v.z), h3 = __float2bfloat16(v.w);
    bf162 hh[2] = { __halves2bfloat162(h0, h1), __halves2bfloat162(h2, h3) };
    bf162 ll[2] = {
        __halves2bfloat162(__float2bfloat16(v.x - __bfloat162float(h0)),
                           __float2bfloat16(v.y - __bfloat162float(h1))),
        __halves2bfloat162(__float2bfloat16(v.z - __bfloat162float(h2)),
                           __float2bfloat16(v.w - __bfloat162float(h3))) };
    h[i] = *(uint2*)hh;
    l[i] = *(uint2*)ll;
}

// W[K][N] fp32  ->  h/l[N][K] bf16 (transposed split)
__global__ void tsplit_kernel(const float* __restrict__ W, bf16* __restrict__ h,
                              bf16* __restrict__ l, int K, int N)
{
    int idx = blockIdx.x * blockDim.x + threadIdx.x;
    if (idx >= K * N) return;
    int k = idx / N, n = idx - k * N;
    float v = W[idx];
    bf16 hh = __float2bfloat16(v);
    h[(size_t)n * K + k] = hh;
    l[(size_t)n * K + k] = __float2bfloat16(v - __bfloat162float(hh));
}

// T[t][j] = b1e[j] + sum_k e_emb[t][k] * W1e[k][j]   (rows 0..127 of W1e, fp32)
__global__ void type_table_kernel(const float* __restrict__ e_emb,
                                  const float* __restrict__ W1e,
                                  const float* __restrict__ b1e)
{
    int idx = blockIdx.x * blockDim.x + threadIdx.x;
    if (idx >= N_TYPES * H_E) return;
    int t = idx / H_E;
    int j = idx - t * H_E;
    float acc = b1e[j];
    const float* er = e_emb + t * IN_DIM;
#pragma unroll 16
    for (int k = 0; k < IN_DIM; k++)
        acc = fmaf(er[k], W1e[(size_t)k * H_E + j], acc);
    g_T[idx] = acc;
}

// ---------------------------------------------------------------------------
// CSR build: histogram -> hierarchical scan (3 tiny kernels) -> scatter
// ---------------------------------------------------------------------------
__global__ void hist_kernel(const int* __restrict__ dst, int E)
{
    int i = blockIdx.x * blockDim.x + threadIdx.x;
    if (i < E) atomicAdd(&g_cnt[dst[i]], 1);
}

// Stage 1: per-256-chunk sums.  grid = ceil(n/256)
__global__ void scan1_kernel(int n)
{
    __shared__ int s[256];
    const int i = blockIdx.x * 256 + threadIdx.x;
    s[threadIdx.x] = (i < n) ? g_cnt[i] : 0;
    __syncthreads();
#pragma unroll
    for (int d = 128; d > 0; d >>= 1) {
        if (threadIdx.x < d) s[threadIdx.x] += s[threadIdx.x + d];
        __syncthreads();
    }
    if (threadIdx.x == 0) g_bsum[blockIdx.x] = s[0];
}

// Stage 2: scan the (<=256) block sums.  1 block x 256 threads.
__global__ void scan2_kernel(int nb, int n, int E)
{
    __shared__ int s[256];
    const int t = threadIdx.x;
    s[t] = (t < nb) ? g_bsum[t] : 0;
    __syncthreads();
#pragma unroll
    for (int d = 1; d < 256; d <<= 1) {
        int v = (t >= d) ? s[t - d] : 0;
        __syncthreads();
        s[t] += v;
        __syncthreads();
    }
    if (t < nb) g_boff[t] = (t == 0) ? 0 : s[t - 1];   // exclusive
    if (t == 0) g_off[n] = E;
}

// Stage 3: in-block exclusive scan + block offset.  grid = ceil(n/256)
__global__ void scan3_kernel(int n)
{
    __shared__ int s[256];
    const int i = blockIdx.x * 256 + threadIdx.x;
    const int v = (i < n) ? g_cnt[i] : 0;
    s[threadIdx.x] = v;
    __syncthreads();
#pragma unroll
    for (int d = 1; d < 256; d <<= 1) {
        int x = (threadIdx.x >= d) ? s[threadIdx.x - d] : 0;
        __syncthreads();
        s[threadIdx.x] += x;
        __syncthreads();
    }
    if (i < n) {
        const int off = g_boff[blockIdx.x] + s[threadIdx.x] - v;  // exclusive
        g_off[i] = off;
        g_cur[i] = off;
    }
}

__global__ void scatter_kernel(const int* __restrict__ src,
                               const int* __restrict__ dst,
                               const int* __restrict__ typ, int E)
{
    int i = blockIdx.x * blockDim.x + threadIdx.x;
    if (i >= E) return;
    int p = atomicAdd(&g_cur[dst[i]], 1);
    g_edges[p] = src[i] | (typ[i] << 20);
}

// ---------------------------------------------------------------------------
// Gather (no atomics): TWO warps per dst node, depth-2 pipeline, GRID-STRIDE
// persistent blocks (proven R11 version).
// ---------------------------------------------------------------------------
__global__ __launch_bounds__(256)
void gather_kernel(int n_nodes)
{
    __shared__ float4 sT[N_TYPES * (H_E / 4)];   // 32 KB
    for (int i = threadIdx.x; i < N_TYPES * (H_E / 4); i += blockDim.x)
        sT[i] = ((const float4*)g_T)[i];
    __syncthreads();

    const int lane = threadIdx.x & 31;
    const int warps_total = (gridDim.x * blockDim.x) >> 5;
    const int gw0 = (blockIdx.x * blockDim.x + threadIdx.x) >> 5;
    const int* __restrict__ edges = g_edges;

    for (int gw = gw0; (gw >> 1) < n_nodes; gw += warps_total) {
        const int d = gw >> 1;
        const int half = gw & 1;

        const int beg = g_off[d];
        const int end = g_off[d + 1];
        const int coff = half * (H_E / 2) + lane * 8;

        const bf16* __restrict__ Fbase = g_Fb + coff;
        const float4* __restrict__ Tbase = sT + (coff >> 2);

        float acc[8];
#pragma unroll
        for (int i = 0; i < 8; i++) acc[i] = 0.f;

        uint4 qa, qb;
        int ta = 0, tb = 0;
        if (beg < end) {
            int p = edges[beg];
            ta = p >> 20;
            qa = *(const uint4*)(Fbase + (size_t)(p & 0xFFFFF) * H_E);
        }
        if (beg + 1 < end) {
            int p = edges[beg + 1];
            tb = p >> 20;
            qb = *(const uint4*)(Fbase + (size_t)(p & 0xFFFFF) * H_E);
        }

        for (int e = beg; e < end; e++) {
            uint4 qn; int tn = 0;
            if (e + 2 < end) {
                int p = edges[e + 2];
                tn = p >> 20;
                qn = *(const uint4*)(Fbase + (size_t)(p & 0xFFFFF) * H_E);
            }
            const float4* Tr = Tbase + ta * (H_E / 4);
            float4 t0 = Tr[0], t1 = Tr[1];
            const bf162* bq = (const bf162*)&qa;
            float2 f;
            f = __bfloat1622float2(bq[0]); acc[0] += fmaxf(f.x + t0.x, 0.f); acc[1] += fmaxf(f.y + t0.y, 0.f);
            f = __bfloat1622float2(bq[1]); acc[2] += fmaxf(f.x + t0.z, 0.f); acc[3] += fmaxf(f.y + t0.w, 0.f);
            f = __bfloat1622float2(bq[2]); acc[4] += fmaxf(f.x + t1.x, 0.f); acc[5] += fmaxf(f.y + t1.y, 0.f);
            f = __bfloat1622float2(bq[3]); acc[6] += fmaxf(f.x + t1.z, 0.f); acc[7] += fmaxf(f.y + t1.w, 0.f);
            qa = qb; ta = tb;
            qb = qn; tb = tn;
        }

        bf162 hh[4], ll[4];
#pragma unroll
        for (int i = 0; i < 4; i++) {
            bf16 h0 = __float2bfloat16(acc[2 * i]);
            bf16 h1 = __float2bfloat16(acc[2 * i + 1]);
            float l0 = acc[2 * i]     - __bfloat162float(h0);
            float l1 = acc[2 * i + 1] - __bfloat162float(h1);
            hh[i] = __halves2bfloat162(h0, h1);
            ll[i] = __halves2bfloat162(__float2bfloat16(l0), __float2bfloat16(l1));
        }
        *(uint4*)(g_Hh + (size_t)d * H_E + coff) = *(uint4*)hh;
        *(uint4*)(g_Hl + (size_t)d * H_E + coff) = *(uint4*)ll;
        if (lane == 0 && half == 0) g_deg[d] = end - beg;
    }
}

// ---------------------------------------------------------------------------
// 3-term bf16 tensor-core GEMM (fp32-emulated): C = Ah*Bh + Ah*Bl + Al*Bh
// Operands PRE-SPLIT in gmem: A[M][K] h/l, B[N][K] h/l (pre-transposed).
// 128x128 tile, BK=32, 256 thr (8 warps, 2Mx4N), cp.async double buffer.
// Fragment loads via ldmatrix.m8n8.x4 (conflict-free: 80B row stride).
// MODE: 0 = fp32 C;  1 = split bf16 Ch/Cl;  2 = single bf16 Ch.
// ---------------------------------------------------------------------------
#define BM 128
#define BN 128
#define BK 32
#define LDA 40                 // bf16 row stride (+8 pad); 80B: 8 rows -> 8 distinct 16B banks
#define MAT_ELEMS (BM * LDA)   // 5120 bf16 per matrix per stage
#define STAGE_ELEMS (4 * MAT_ELEMS)
#define GEMM_SMEM (2 * STAGE_ELEMS * 2)   // bytes = 81920

__device__ __forceinline__ void cpa16(bf16* s, const bf16* g, bool p)
{
    uint32_t sa = (uint32_t)__cvta_generic_to_shared(s);
    int sz = p ? 16 : 0;
    asm volatile("cp.async.ca.shared.global [%0], [%1], 16, %2;\n"
                 :: "r"(sa), "l"(g), "r"(sz));
}

__device__ __forceinline__ void ldm4(uint32_t* r, const bf16* p)
{
    uint32_t a = (uint32_t)__cvta_generic_to_shared(p);
    asm volatile("ldmatrix.sync.aligned.m8n8.x4.shared.b16 {%0,%1,%2,%3}, [%4];\n"
                 : "=r"(r[0]), "=r"(r[1]), "=r"(r[2]), "=r"(r[3]) : "r"(a));
}

__device__ __forceinline__ void bmma(float* c, const uint32_t* a,
                                     uint32_t b0, uint32_t b1)
{
    asm volatile(
        "mma.sync.aligned.m16n8k16.row.col.f32.bf16.bf16.f32 "
        "{%0,%1,%2,%3}, {%4,%5,%6,%7}, {%8,%9}, {%0,%1,%2,%3};\n"
        : "+f"(c[0]), "+f"(c[1]), "+f"(c[2]), "+f"(c[3])
        : "r"(a[0]), "r"(a[1]), "r"(a[2]), "r"(a[3]), "r"(b0), "r"(b1));
}

template<int MODE, bool RELU>
__global__ __launch_bounds__(256)
void gemm_bf3(const bf16* __restrict__ Ah, const bf16* __restrict__ Al,
              const bf16* __restrict__ Bh, const bf16* __restrict__ Bl,
              float* __restrict__ C, bf16* __restrict__ Ch, bf16* __restrict__ Cl,
              int M, int K, int N, int ldc,
              const float* __restrict__ bias,
              const int* __restrict__ rowcnt, const float* __restrict__ rowvec)
{
    extern __shared__ bf16 smem[];
    const int tid = threadIdx.x;
    const int bm = blockIdx.x * BM;
    const int bn = blockIdx.y * BN;
    const int warp = tid >> 5, lane = tid & 31;
    const int wm = (warp >> 2) * 64;
    const int wn = (warp & 3) * 32;
    const int g  = lane >> 2;
    const int tg = lane & 3;
    const int lrow = lane & 15;
    const int lkh  = (lane >> 4) * 8;

    float c[4][4][4];
#pragma unroll
    for (int mt = 0; mt < 4; mt++)
#pragma unroll
        for (int nt = 0; nt < 4; nt++)
#pragma unroll
            for (int u = 0; u < 4; u++) c[mt][nt][u] = 0.f;

    const int ntile = K / BK;

    auto load_stage = [&](int buf, int k0) {
        bf16* s = smem + buf * STAGE_ELEMS;
#pragma unroll
        for (int j = 0; j < 2; j++) {
            const int idx = tid + j * 256;        // 0..511
            const int row = idx >> 2;
            const int ch  = idx & 3;
            const bool p = (bm + row) < M;
            const size_t ga = (size_t)(bm + row) * K + k0 + ch * 8;
            cpa16(s + row * LDA + ch * 8,                 Ah + ga, p);
            cpa16(s + MAT_ELEMS + row * LDA + ch * 8,     Al + ga, p);
            const size_t gb = (size_t)(bn + row) * K + k0 + ch * 8;
            cpa16(s + 2 * MAT_ELEMS + row * LDA + ch * 8, Bh + gb, true);
            cpa16(s + 3 * MAT_ELEMS + row * LDA + ch * 8, Bl + gb, true);
        }
        asm volatile("cp.async.commit_group;\n");
    };

    load_stage(0, 0);

    for (int kt = 0; kt < ntile; kt++) {
        if (kt + 1 < ntile) {
            load_stage((kt + 1) & 1, (kt + 1) * BK);
            asm volatile("cp.async.wait_group 1;\n");
        } else {
            asm volatile("cp.async.wait_group 0;\n");
        }
        __syncthreads();

        const bf16* sAh = smem + (kt & 1) * STAGE_ELEMS;
        const bf16* sAl = sAh + MAT_ELEMS;
        const bf16* sBh = sAh + 2 * MAT_ELEMS;

#pragma unroll
        for (int kk = 0; kk < BK; kk += 16) {
            uint32_t ah[4][4], al[4][4], bh[2][4], bl[2][4];
#pragma unroll
            for (int mt = 0; mt < 4; mt++) {
                const bf16* pa = sAh + (wm + mt * 16 + lrow) * LDA + kk + lkh;
                ldm4(ah[mt], pa);
                ldm4(al[mt], pa + MAT_ELEMS);
            }
#pragma unroll
            for (int n2 = 0; n2 < 2; n2++) {
                const bf16* pb = sBh + (wn + n2 * 16 + lrow) * LDA + kk + lkh;
                ldm4(bh[n2], pb);
                ldm4(bl[n2], pb + MAT_ELEMS);
            }
#pragma unroll
            for (int mt = 0; mt < 4; mt++)
#pragma unroll
                for (int nt = 0; nt < 4; nt++) {
                    const int n2 = nt >> 1, od = nt & 1;
                    bmma(c[mt][nt], ah[mt], bh[n2][od], bh[n2][od + 2]);
                    bmma(c[mt][nt], ah[mt], bl[n2][od], bl[n2][od + 2]);
                    bmma(c[mt][nt], al[mt], bh[n2][od], bh[n2][od + 2]);
                }
        }
        __syncthreads();
    }

    // --- epilogue ---
#pragma unroll
    for (int mt = 0; mt < 4; mt++) {
#pragma unroll
        for (int half = 0; half < 2; half++) {
            const int r = bm + wm + mt * 16 + g + half * 8;
            if (r >= M) continue;
            const float rc = rowcnt ? (float)rowcnt[r] : 0.f;
#pragma unroll
            for (int nt = 0; nt < 4; nt++) {
                const int col = bn + wn + nt * 8 + tg * 2;
                float x0 = c[mt][nt][half * 2 + 0];
                float x1 = c[mt][nt][half * 2 + 1];
                if (bias)   { x0 += bias[col];  x1 += bias[col + 1]; }
                if (rowcnt) { x0 = fmaf(rc, rowvec[col], x0);
                              x1 = fmaf(rc, rowvec[col + 1], x1); }
                if (RELU)   { x0 = fmaxf(x0, 0.f); x1 = fmaxf(x1, 0.f); }
                if (MODE == 0) {
                    *(float2*)(C + (size_t)r * ldc + col) = make_float2(x0, x1);
                } else {
                    bf16 h0 = __float2bfloat16(x0);
                    bf16 h1 = __float2bfloat16(x1);
                    *(bf162*)(Ch + (size_t)r * ldc + col) = __halves2bfloat162(h0, h1);
                    if (MODE == 1) {
                        float l0 = x0 - __bfloat162float(h0);
                        float l1 = x1 - __bfloat162float(h1);
                        *(bf162*)(Cl + (size_t)r * ldc + col) =
                            __halves2bfloat162(__float2bfloat16(l0), __float2bfloat16(l1));
                    }
                }
            }
        }
    }
}

// ---------------------------------------------------------------------------
extern "C" void kernel_launch(void* const* d_in, const int* in_sizes, int n_in,
                              void* d_out, int out_size)
{
    const float* features = (const float*)d_in[0];
    const int*   edge_src = (const int*)  d_in[1];
    const int*   edge_dst = (const int*)  d_in[2];
    const int*   edge_typ = (const int*)  d_in[3];
    const float* e_emb    = (const float*)d_in[4];
    const float* W1e      = (const float*)d_in[5];
    const float* b1e      = (const float*)d_in[6];
    const float* W2e      = (const float*)d_in[7];
    const float* b2e      = (const float*)d_in[8];
    const float* W1s      = (const float*)d_in[9];
    const float* b1s      = (const float*)d_in[10];
    const float* W2s      = (const float*)d_in[11];
    const float* b2s      = (const float*)d_in[12];
    float* out = (float*)d_out;

    const int n_nodes = in_sizes[0] / IN_DIM;
    const int n_edges = in_sizes[1];

    cudaFuncSetAttribute(gemm_bf3<0, false>, cudaFuncAttributeMaxDynamicSharedMemorySize, GEMM_SMEM);
    cudaFuncSetAttribute(gemm_bf3<1, true>,  cudaFuncAttributeMaxDynamicSharedMemorySize, GEMM_SMEM);
    cudaFuncSetAttribute(gemm_bf3<2, false>, cudaFuncAttributeMaxDynamicSharedMemorySize, GEMM_SMEM);

    void *pCnt;
    cudaGetSymbolAddress(&pCnt, g_cnt);
    bf16 *pfh, *pfl, *pW1eh, *pW1el, *pW1sh, *pW1sl, *pW2eh, *pW2el, *pW2sh, *pW2sl;
    bf16 *pFb, *pHh, *pHl, *pShh, *pShl;
    { void* t;
      cudaGetSymbolAddress(&t, g_fh);   pfh   = (bf16*)t;
      cudaGetSymbolAddress(&t, g_fl);   pfl   = (bf16*)t;
      cudaGetSymbolAddress(&t, g_W1eh); pW1eh = (bf16*)t;
      cudaGetSymbolAddress(&t, g_W1el); pW1el = (bf16*)t;
      cudaGetSymbolAddress(&t, g_W1sh); pW1sh = (bf16*)t;
      cudaGetSymbolAddress(&t, g_W1sl); pW1sl = (bf16*)t;
      cudaGetSymbolAddress(&t, g_W2eh); pW2eh = (bf16*)t;
      cudaGetSymbolAddress(&t, g_W2el); pW2el = (bf16*)t;
      cudaGetSymbolAddress(&t, g_W2sh); pW2sh = (bf16*)t;
      cudaGetSymbolAddress(&t, g_W2sl); pW2sl = (bf16*)t;
      cudaGetSymbolAddress(&t, g_Fb);   pFb   = (bf16*)t;
      cudaGetSymbolAddress(&t, g_Hh);   pHh   = (bf16*)t;
      cudaGetSymbolAddress(&t, g_Hl);   pHl   = (bf16*)t;
      cudaGetSymbolAddress(&t, g_Shh);  pShh  = (bf16*)t;
      cudaGetSymbolAddress(&t, g_Shl);  pShl  = (bf16*)t;
    }
    int* pDeg; { void* t; cudaGetSymbolAddress(&t, g_deg); pDeg = (int*)t; }

    // ONE side stream + events (same footprint as the passing runs).
    cudaStream_t s1;
    cudaStreamCreateWithFlags(&s1, cudaStreamNonBlocking);
    cudaEvent_t eStart, eCsr, eSide, eW, eF;
    cudaEventCreateWithFlags(&eStart, cudaEventDisableTiming);
    cudaEventCreateWithFlags(&eCsr,   cudaEventDisableTiming);
    cudaEventCreateWithFlags(&eSide,  cudaEventDisableTiming);
    cudaEventCreateWithFlags(&eW,     cudaEventDisableTiming);
    cudaEventCreateWithFlags(&eF,     cudaEventDisableTiming);

    // ---- fork ----
    cudaEventRecord(eStart, 0);
    cudaStreamWaitEvent(s1, eStart, 0);

    // ---- s1: all weight splits (no deps) -> CSR build + type table ----
    tsplit_kernel<<<(IN_DIM * H_E + 255) / 256, 256, 0, s1>>>(W1e + (size_t)IN_DIM * H_E, pW1eh, pW1el, IN_DIM, H_E);
    tsplit_kernel<<<(H_E * OUT_HALF + 255) / 256, 256, 0, s1>>>(W2e, pW2eh, pW2el, H_E, OUT_HALF);
    cudaEventRecord(eW, s1);
    tsplit_kernel<<<(IN_DIM * H_S + 255) / 256, 256, 0, s1>>>(W1s, pW1sh, pW1sl, IN_DIM, H_S);
    tsplit_kernel<<<(H_S * OUT_HALF + 255) / 256, 256, 0, s1>>>(W2s, pW2sh, pW2sl, H_S, OUT_HALF);
    cudaMemsetAsync(pCnt, 0, (size_t)n_nodes * sizeof(int), s1);
    hist_kernel<<<(n_edges + 255) / 256, 256, 0, s1>>>(edge_dst, n_edges);
    {
        const int nb = (n_nodes + 255) / 256;
        scan1_kernel<<<nb, 256, 0, s1>>>(n_nodes);
        scan2_kernel<<<1, 256, 0, s1>>>(nb, n_nodes, n_edges);
        scan3_kernel<<<nb, 256, 0, s1>>>(n_nodes);
    }
    scatter_kernel<<<(n_edges + 255) / 256, 256, 0, s1>>>(edge_src, edge_dst, edge_typ, n_edges);
    type_table_kernel<<<(N_TYPES * H_E + 255) / 256, 256, 0, s1>>>(e_emb, W1e, b1e);
    cudaEventRecord(eCsr, s1);

    // ---- main: feature split -> F-GEMM (tensor units exclusively) ----
    {
        const int n4 = n_nodes * IN_DIM / 4;
        split_kernel<<<(n4 + 255) / 256, 256>>>((const float4*)features,
                                                (uint2*)pfh, (uint2*)pfl, n4);
    }
    cudaStreamWaitEvent(0, eW, 0);

    const int gm = (n_nodes + BM - 1) / BM;

    // F = feat @ W1e_bot  ->  single bf16 [N,512]
    {
        dim3 grid(gm, H_E / BN);
        gemm_bf3<2, false><<<grid, 256, GEMM_SMEM>>>(
            pfh, pfl, pW1eh, pW1el, nullptr, pFb, nullptr,
            n_nodes, IN_DIM, H_E, H_E, nullptr, nullptr, nullptr);
    }
    cudaEventRecord(eF, 0);

    // ---- s1: self-path GEMMs DURING the gather window (tensor idle there) ----
    cudaStreamWaitEvent(s1, eF, 0);
    {
        dim3 grid(gm, H_S / BN);
        gemm_bf3<1, true><<<grid, 256, GEMM_SMEM, s1>>>(
            pfh, pfl, pW1sh, pW1sl, nullptr, pShh, pShl,
            n_nodes, IN_DIM, H_S, H_S, b1s, nullptr, nullptr);
    }
    {
        dim3 grid(gm, 1);
        gemm_bf3<0, false><<<grid, 256, GEMM_SMEM, s1>>>(
            pShh, pShl, pW2sh, pW2sl, out, nullptr, nullptr,
            n_nodes, H_S, OUT_HALF, 2 * OUT_HALF, b2s, nullptr, nullptr);
    }
    cudaEventRecord(eSide, s1);

    // ---- main: gather (needs CSR + T, both long done) -> W2e-GEMM ----
    cudaStreamWaitEvent(0, eCsr, 0);
    gather_kernel<<<1184, 256>>>(n_nodes);

    // out[:, 128:256] = H @ W2e + deg*b2e
    {
        dim3 grid(gm, 1);
        gemm_bf3<0, false><<<grid, 256, GEMM_SMEM>>>(
            pHh, pHl, pW2eh, pW2el, out + OUT_HALF, nullptr, nullptr,
            n_nodes, H_E, OUT_HALF, 2 * OUT_HALF, nullptr, pDeg, b2e);
    }

    // ---- join ----
    cudaStreamWaitEvent(0, eSide, 0);
}

// round 17
// speedup vs baseline: 1.0429x; 1.0429x over previous
#include <cuda_runtime.h>
#include <cuda_bf16.h>
#include <cstdint>
#include <cstddef>

// Problem constants (fixed by the dataset instance)
#define IN_DIM   128
#define H_E      512     // 2*IN_DIM*SCALE
#define H_S      256     // IN_DIM*SCALE
#define OUT_HALF 128
#define N_TYPES  16
#define MAX_NODES 50000
#define MAX_EDGES 400000

typedef __nv_bfloat16  bf16;
typedef __nv_bfloat162 bf162;

// Scratch (allocation-free rule: __device__ globals)
__device__ bf16  g_Fb [MAX_NODES * H_E];      // F = feat@W1e_bot, single bf16 [N,512]
__device__ bf16  g_Hh [MAX_NODES * H_E];      // H hi  [N,512]
__device__ bf16  g_Hl [MAX_NODES * H_E];      // H lo  [N,512]
__device__ bf16  g_Shh[MAX_NODES * H_S];      // Sh hi [N,256]
__device__ bf16  g_Shl[MAX_NODES * H_S];      // Sh lo [N,256]
__device__ bf16  g_fh [MAX_NODES * IN_DIM];   // features hi [N,128]
__device__ bf16  g_fl [MAX_NODES * IN_DIM];   // features lo [N,128]
// transposed split weights: [n][k]
__device__ bf16  g_W1eh[H_E * IN_DIM],   g_W1el[H_E * IN_DIM];
__device__ bf16  g_W1sh[H_S * IN_DIM],   g_W1sl[H_S * IN_DIM];
__device__ bf16  g_W2eh[OUT_HALF * H_E], g_W2el[OUT_HALF * H_E];
__device__ bf16  g_W2sh[OUT_HALF * H_S], g_W2sl[OUT_HALF * H_S];
__device__ float g_T [N_TYPES * H_E];         // e_emb@W1e_top + b1e  (fp32)
__device__ int   g_deg[MAX_NODES];
__device__ int   g_cnt[MAX_NODES];
__device__ int   g_off[MAX_NODES + 1];
__device__ int   g_cur[MAX_NODES];
__device__ int   g_bsum[256];                 // per-block sums for scan
__device__ int   g_boff[256];                 // per-block exclusive offsets
__device__ int   g_edges[MAX_EDGES];          // packed: src | (type << 20)

// ---------------------------------------------------------------------------
// Conversion kernels (run once per launch, tiny)
// ---------------------------------------------------------------------------
__global__ void split_kernel(const float4* __restrict__ x, uint2* __restrict__ h,
                             uint2* __restrict__ l, int n4)
{
    int i = blockIdx.x * blockDim.x + threadIdx.x;
    if (i >= n4) return;
    float4 v = x[i];
    bf16 h0 = __float2bfloat16(v.x), h1 = __float2bfloat16(v.y);
    bf16 h2 = __float2bfloat16(v.z), h3 = __float2bfloat16(v.w);
    bf162 hh[2] = { __halves2bfloat162(h0, h1), __halves2bfloat162(h2, h3) };
    bf162 ll[2] = {
        __halves2bfloat162(__float2bfloat16(v.x - __bfloat162float(h0)),
                           __float2bfloat16(v.y - __bfloat162float(h1))),
        __halves2bfloat162(__float2bfloat16(v.z - __bfloat162float(h2)),
                           __float2bfloat16(v.w - __bfloat162float(h3))) };
    h[i] = *(uint2*)hh;
    l[i] = *(uint2*)ll;
}

// W[K][N] fp32  ->  h/l[N][K] bf16 (transposed split)
__global__ void tsplit_kernel(const float* __restrict__ W, bf16* __restrict__ h,
                              bf16* __restrict__ l, int K, int N)
{
    int idx = blockIdx.x * blockDim.x + threadIdx.x;
    if (idx >= K * N) return;
    int k = idx / N, n = idx - k * N;
    float v = W[idx];
    bf16 hh = __float2bfloat16(v);
    h[(size_t)n * K + k] = hh;
    l[(size_t)n * K + k] = __float2bfloat16(v - __bfloat162float(hh));
}

// T[t][j] = b1e[j] + sum_k e_emb[t][k] * W1e[k][j]   (rows 0..127 of W1e, fp32)
__global__ void type_table_kernel(const float* __restrict__ e_emb,
                                  const float* __restrict__ W1e,
                                  const float* __restrict__ b1e)
{
    int idx = blockIdx.x * blockDim.x + threadIdx.x;
    if (idx >= N_TYPES * H_E) return;
    int t = idx / H_E;
    int j = idx - t * H_E;
    float acc = b1e[j];
    const float* er = e_emb + t * IN_DIM;
#pragma unroll 16
    for (int k = 0; k < IN_DIM; k++)
        acc = fmaf(er[k], W1e[(size_t)k * H_E + j], acc);
    g_T[idx] = acc;
}

// ---------------------------------------------------------------------------
// CSR build: histogram -> hierarchical scan (3 tiny kernels) -> scatter
// ---------------------------------------------------------------------------
__global__ void hist_kernel(const int* __restrict__ dst, int E)
{
    int i = blockIdx.x * blockDim.x + threadIdx.x;
    if (i < E) atomicAdd(&g_cnt[dst[i]], 1);
}

// Stage 1: per-256-chunk sums.  grid = ceil(n/256)
__global__ void scan1_kernel(int n)
{
    __shared__ int s[256];
    const int i = blockIdx.x * 256 + threadIdx.x;
    s[threadIdx.x] = (i < n) ? g_cnt[i] : 0;
    __syncthreads();
#pragma unroll
    for (int d = 128; d > 0; d >>= 1) {
        if (threadIdx.x < d) s[threadIdx.x] += s[threadIdx.x + d];
        __syncthreads();
    }
    if (threadIdx.x == 0) g_bsum[blockIdx.x] = s[0];
}

// Stage 2: scan the (<=256) block sums.  1 block x 256 threads.
__global__ void scan2_kernel(int nb, int n, int E)
{
    __shared__ int s[256];
    const int t = threadIdx.x;
    s[t] = (t < nb) ? g_bsum[t] : 0;
    __syncthreads();
#pragma unroll
    for (int d = 1; d < 256; d <<= 1) {
        int v = (t >= d) ? s[t - d] : 0;
        __syncthreads();
        s[t] += v;
        __syncthreads();
    }
    if (t < nb) g_boff[t] = (t == 0) ? 0 : s[t - 1];   // exclusive
    if (t == 0) g_off[n] = E;
}

// Stage 3: in-block exclusive scan + block offset.  grid = ceil(n/256)
__global__ void scan3_kernel(int n)
{
    __shared__ int s[256];
    const int i = blockIdx.x * 256 + threadIdx.x;
    const int v = (i < n) ? g_cnt[i] : 0;
    s[threadIdx.x] = v;
    __syncthreads();
#pragma unroll
    for (int d = 1; d < 256; d <<= 1) {
        int x = (threadIdx.x >= d) ? s[threadIdx.x - d] : 0;
        __syncthreads();
        s[threadIdx.x] += x;
        __syncthreads();
    }
    if (i < n) {
        const int off = g_boff[blockIdx.x] + s[threadIdx.x] - v;  // exclusive
        g_off[i] = off;
        g_cur[i] = off;
    }
}

__global__ void scatter_kernel(const int* __restrict__ src,
                               const int* __restrict__ dst,
                               const int* __restrict__ typ, int E)
{
    int i = blockIdx.x * blockDim.x + threadIdx.x;
    if (i >= E) return;
    int p = atomicAdd(&g_cur[dst[i]], 1);
    g_edges[p] = src[i] | (typ[i] << 20);
}

// ---------------------------------------------------------------------------
// Gather (no atomics): ONE warp per dst node owning the full 512-col row.
// Each lane: 2 independent uint4 loads per edge (cols lane*8 and 256+lane*8),
// depth-2 software pipeline -> 4 outstanding loads per warp.
// Accumulation order over edges is sequential (numerics identical to R11).
// ---------------------------------------------------------------------------
__global__ __launch_bounds__(256)
void gather_kernel(int n_nodes)
{
    __shared__ float4 sT[N_TYPES * (H_E / 4)];   // 32 KB
    for (int i = threadIdx.x; i < N_TYPES * (H_E / 4); i += blockDim.x)
        sT[i] = ((const float4*)g_T)[i];
    __syncthreads();

    const int lane = threadIdx.x & 31;
    const int warps_total = (gridDim.x * blockDim.x) >> 5;
    const int gw0 = (blockIdx.x * blockDim.x + threadIdx.x) >> 5;
    const int* __restrict__ edges = g_edges;

    const int c0 = lane * 8;               // first 8-col group
    const int c1 = 256 + lane * 8;         // second 8-col group
    const bf16* __restrict__ F0 = g_Fb + c0;
    const bf16* __restrict__ F1 = g_Fb + c1;
    const float4* __restrict__ T0 = sT + (c0 >> 2);
    const float4* __restrict__ T1 = sT + (c1 >> 2);

    for (int d = gw0; d < n_nodes; d += warps_total) {
        const int beg = g_off[d];
        const int end = g_off[d + 1];

        float acc[16];
#pragma unroll
        for (int i = 0; i < 16; i++) acc[i] = 0.f;

        // depth-2 pipeline, 2 independent loads per stage
        uint4 qa0, qa1, qb0, qb1;
        int ta = 0, tb = 0;
        if (beg < end) {
            int p = edges[beg];
            ta = p >> 20;
            const size_t r = (size_t)(p & 0xFFFFF) * H_E;
            qa0 = *(const uint4*)(F0 + r);
            qa1 = *(const uint4*)(F1 + r);
        }
        if (beg + 1 < end) {
            int p = edges[beg + 1];
            tb = p >> 20;
            const size_t r = (size_t)(p & 0xFFFFF) * H_E;
            qb0 = *(const uint4*)(F0 + r);
            qb1 = *(const uint4*)(F1 + r);
        }

        for (int e = beg; e < end; e++) {
            uint4 qn0, qn1; int tn = 0;
            if (e + 2 < end) {
                int p = edges[e + 2];
                tn = p >> 20;
                const size_t r = (size_t)(p & 0xFFFFF) * H_E;
                qn0 = *(const uint4*)(F0 + r);
                qn1 = *(const uint4*)(F1 + r);
            }
            const float4* Tr0 = T0 + ta * (H_E / 4);
            const float4* Tr1 = T1 + ta * (H_E / 4);
            float4 t0 = Tr0[0], t1 = Tr0[1];
            float4 t2 = Tr1[0], t3 = Tr1[1];
            const bf162* b0 = (const bf162*)&qa0;
            const bf162* b1 = (const bf162*)&qa1;
            float2 f;
            f = __bfloat1622float2(b0[0]); acc[0]  += fmaxf(f.x + t0.x, 0.f); acc[1]  += fmaxf(f.y + t0.y, 0.f);
            f = __bfloat1622float2(b0[1]); acc[2]  += fmaxf(f.x + t0.z, 0.f); acc[3]  += fmaxf(f.y + t0.w, 0.f);
            f = __bfloat1622float2(b0[2]); acc[4]  += fmaxf(f.x + t1.x, 0.f); acc[5]  += fmaxf(f.y + t1.y, 0.f);
            f = __bfloat1622float2(b0[3]); acc[6]  += fmaxf(f.x + t1.z, 0.f); acc[7]  += fmaxf(f.y + t1.w, 0.f);
            f = __bfloat1622float2(b1[0]); acc[8]  += fmaxf(f.x + t2.x, 0.f); acc[9]  += fmaxf(f.y + t2.y, 0.f);
            f = __bfloat1622float2(b1[1]); acc[10] += fmaxf(f.x + t2.z, 0.f); acc[11] += fmaxf(f.y + t2.w, 0.f);
            f = __bfloat1622float2(b1[2]); acc[12] += fmaxf(f.x + t3.x, 0.f); acc[13] += fmaxf(f.y + t3.y, 0.f);
            f = __bfloat1622float2(b1[3]); acc[14] += fmaxf(f.x + t3.z, 0.f); acc[15] += fmaxf(f.y + t3.w, 0.f);
            qa0 = qb0; qa1 = qb1; ta = tb;
            qb0 = qn0; qb1 = qn1; tb = tn;
        }

        bf162 hh[8], ll[8];
#pragma unroll
        for (int i = 0; i < 8; i++) {
            bf16 h0 = __float2bfloat16(acc[2 * i]);
            bf16 h1 = __float2bfloat16(acc[2 * i + 1]);
            float l0 = acc[2 * i]     - __bfloat162float(h0);
            float l1 = acc[2 * i + 1] - __bfloat162float(h1);
            hh[i] = __halves2bfloat162(h0, h1);
            ll[i] = __halves2bfloat162(__float2bfloat16(l0), __float2bfloat16(l1));
        }
        const size_t hr = (size_t)d * H_E;
        *(uint4*)(g_Hh + hr + c0) = *(uint4*)&hh[0];
        *(uint4*)(g_Hh + hr + c1) = *(uint4*)&hh[4];
        *(uint4*)(g_Hl + hr + c0) = *(uint4*)&ll[0];
        *(uint4*)(g_Hl + hr + c1) = *(uint4*)&ll[4];
        if (lane == 0) g_deg[d] = end - beg;
    }
}

// ---------------------------------------------------------------------------
// 3-term bf16 tensor-core GEMM (fp32-emulated): C = Ah*Bh + Ah*Bl + Al*Bh
// Operands PRE-SPLIT in gmem: A[M][K] h/l, B[N][K] h/l (pre-transposed).
// 128x128 tile, BK=32, 256 thr (8 warps, 2Mx4N), cp.async double buffer.
// Fragment loads via ldmatrix.m8n8.x4 (conflict-free: 80B row stride).
// MODE: 0 = fp32 C;  1 = split bf16 Ch/Cl;  2 = single bf16 Ch.
// ---------------------------------------------------------------------------
#define BM 128
#define BN 128
#define BK 32
#define LDA 40                 // bf16 row stride (+8 pad); 80B: 8 rows -> 8 distinct 16B banks
#define MAT_ELEMS (BM * LDA)   // 5120 bf16 per matrix per stage
#define STAGE_ELEMS (4 * MAT_ELEMS)
#define GEMM_SMEM (2 * STAGE_ELEMS * 2)   // bytes = 81920

__device__ __forceinline__ void cpa16(bf16* s, const bf16* g, bool p)
{
    uint32_t sa = (uint32_t)__cvta_generic_to_shared(s);
    int sz = p ? 16 : 0;
    asm volatile("cp.async.ca.shared.global [%0], [%1], 16, %2;\n"
                 :: "r"(sa), "l"(g), "r"(sz));
}

__device__ __forceinline__ void ldm4(uint32_t* r, const bf16* p)
{
    uint32_t a = (uint32_t)__cvta_generic_to_shared(p);
    asm volatile("ldmatrix.sync.aligned.m8n8.x4.shared.b16 {%0,%1,%2,%3}, [%4];\n"
                 : "=r"(r[0]), "=r"(r[1]), "=r"(r[2]), "=r"(r[3]) : "r"(a));
}

__device__ __forceinline__ void bmma(float* c, const uint32_t* a,
                                     uint32_t b0, uint32_t b1)
{
    asm volatile(
        "mma.sync.aligned.m16n8k16.row.col.f32.bf16.bf16.f32 "
        "{%0,%1,%2,%3}, {%4,%5,%6,%7}, {%8,%9}, {%0,%1,%2,%3};\n"
        : "+f"(c[0]), "+f"(c[1]), "+f"(c[2]), "+f"(c[3])
        : "r"(a[0]), "r"(a[1]), "r"(a[2]), "r"(a[3]), "r"(b0), "r"(b1));
}

template<int MODE, bool RELU>
__global__ __launch_bounds__(256)
void gemm_bf3(const bf16* __restrict__ Ah, const bf16* __restrict__ Al,
              const bf16* __restrict__ Bh, const bf16* __restrict__ Bl,
              float* __restrict__ C, bf16* __restrict__ Ch, bf16* __restrict__ Cl,
              int M, int K, int N, int ldc,
              const float* __restrict__ bias,
              const int* __restrict__ rowcnt, const float* __restrict__ rowvec)
{
    extern __shared__ bf16 smem[];
    const int tid = threadIdx.x;
    const int bm = blockIdx.x * BM;
    const int bn = blockIdx.y * BN;
    const int warp = tid >> 5, lane = tid & 31;
    const int wm = (warp >> 2) * 64;
    const int wn = (warp & 3) * 32;
    const int g  = lane >> 2;
    const int tg = lane & 3;
    const int lrow = lane & 15;
    const int lkh  = (lane >> 4) * 8;

    float c[4][4][4];
#pragma unroll
    for (int mt = 0; mt < 4; mt++)
#pragma unroll
        for (int nt = 0; nt < 4; nt++)
#pragma unroll
            for (int u = 0; u < 4; u++) c[mt][nt][u] = 0.f;

    const int ntile = K / BK;

    auto load_stage = [&](int buf, int k0) {
        bf16* s = smem + buf * STAGE_ELEMS;
#pragma unroll
        for (int j = 0; j < 2; j++) {
            const int idx = tid + j * 256;        // 0..511
            const int row = idx >> 2;
            const int ch  = idx & 3;
            const bool p = (bm + row) < M;
            const size_t ga = (size_t)(bm + row) * K + k0 + ch * 8;
            cpa16(s + row * LDA + ch * 8,                 Ah + ga, p);
            cpa16(s + MAT_ELEMS + row * LDA + ch * 8,     Al + ga, p);
            const size_t gb = (size_t)(bn + row) * K + k0 + ch * 8;
            cpa16(s + 2 * MAT_ELEMS + row * LDA + ch * 8, Bh + gb, true);
            cpa16(s + 3 * MAT_ELEMS + row * LDA + ch * 8, Bl + gb, true);
        }
        asm volatile("cp.async.commit_group;\n");
    };

    load_stage(0, 0);

    for (int kt = 0; kt < ntile; kt++) {
        if (kt + 1 < ntile) {
            load_stage((kt + 1) & 1, (kt + 1) * BK);
            asm volatile("cp.async.wait_group 1;\n");
        } else {
            asm volatile("cp.async.wait_group 0;\n");
        }
        __syncthreads();

        const bf16* sAh = smem + (kt & 1) * STAGE_ELEMS;
        const bf16* sAl = sAh + MAT_ELEMS;
        const bf16* sBh = sAh + 2 * MAT_ELEMS;

#pragma unroll
        for (int kk = 0; kk < BK; kk += 16) {
            uint32_t ah[4][4], al[4][4], bh[2][4], bl[2][4];
#pragma unroll
            for (int mt = 0; mt < 4; mt++) {
                const bf16* pa = sAh + (wm + mt * 16 + lrow) * LDA + kk + lkh;
                ldm4(ah[mt], pa);
                ldm4(al[mt], pa + MAT_ELEMS);
            }
#pragma unroll
            for (int n2 = 0; n2 < 2; n2++) {
                const bf16* pb = sBh + (wn + n2 * 16 + lrow) * LDA + kk + lkh;
                ldm4(bh[n2], pb);
                ldm4(bl[n2], pb + MAT_ELEMS);
            }
#pragma unroll
            for (int mt = 0; mt < 4; mt++)
#pragma unroll
                for (int nt = 0; nt < 4; nt++) {
                    const int n2 = nt >> 1, od = nt & 1;
                    bmma(c[mt][nt], ah[mt], bh[n2][od], bh[n2][od + 2]);
                    bmma(c[mt][nt], ah[mt], bl[n2][od], bl[n2][od + 2]);
                    bmma(c[mt][nt], al[mt], bh[n2][od], bh[n2][od + 2]);
                }
        }
        __syncthreads();
    }

    // --- epilogue ---
#pragma unroll
    for (int mt = 0; mt < 4; mt++) {
#pragma unroll
        for (int half = 0; half < 2; half++) {
            const int r = bm + wm + mt * 16 + g + half * 8;
            if (r >= M) continue;
            const float rc = rowcnt ? (float)rowcnt[r] : 0.f;
#pragma unroll
            for (int nt = 0; nt < 4; nt++) {
                const int col = bn + wn + nt * 8 + tg * 2;
                float x0 = c[mt][nt][half * 2 + 0];
                float x1 = c[mt][nt][half * 2 + 1];
                if (bias)   { x0 += bias[col];  x1 += bias[col + 1]; }
                if (rowcnt) { x0 = fmaf(rc, rowvec[col], x0);
                              x1 = fmaf(rc, rowvec[col + 1], x1); }
                if (RELU)   { x0 = fmaxf(x0, 0.f); x1 = fmaxf(x1, 0.f); }
                if (MODE == 0) {
                    *(float2*)(C + (size_t)r * ldc + col) = make_float2(x0, x1);
                } else {
                    bf16 h0 = __float2bfloat16(x0);
                    bf16 h1 = __float2bfloat16(x1);
                    *(bf162*)(Ch + (size_t)r * ldc + col) = __halves2bfloat162(h0, h1);
                    if (MODE == 1) {
                        float l0 = x0 - __bfloat162float(h0);
                        float l1 = x1 - __bfloat162float(h1);
                        *(bf162*)(Cl + (size_t)r * ldc + col) =
                            __halves2bfloat162(__float2bfloat16(l0), __float2bfloat16(l1));
                    }
                }
            }
        }
    }
}

// ---------------------------------------------------------------------------
extern "C" void kernel_launch(void* const* d_in, const int* in_sizes, int n_in,
                              void* d_out, int out_size)
{
    const float* features = (const float*)d_in[0];
    const int*   edge_src = (const int*)  d_in[1];
    const int*   edge_dst = (const int*)  d_in[2];
    const int*   edge_typ = (const int*)  d_in[3];
    const float* e_emb    = (const float*)d_in[4];
    const float* W1e      = (const float*)d_in[5];
    const float* b1e      = (const float*)d_in[6];
    const float* W2e      = (const float*)d_in[7];
    const float* b2e      = (const float*)d_in[8];
    const float* W1s      = (const float*)d_in[9];
    const float* b1s      = (const float*)d_in[10];
    const float* W2s      = (const float*)d_in[11];
    const float* b2s      = (const float*)d_in[12];
    float* out = (float*)d_out;

    const int n_nodes = in_sizes[0] / IN_DIM;
    const int n_edges = in_sizes[1];

    cudaFuncSetAttribute(gemm_bf3<0, false>, cudaFuncAttributeMaxDynamicSharedMemorySize, GEMM_SMEM);
    cudaFuncSetAttribute(gemm_bf3<1, true>,  cudaFuncAttributeMaxDynamicSharedMemorySize, GEMM_SMEM);
    cudaFuncSetAttribute(gemm_bf3<2, false>, cudaFuncAttributeMaxDynamicSharedMemorySize, GEMM_SMEM);

    void *pCnt;
    cudaGetSymbolAddress(&pCnt, g_cnt);
    bf16 *pfh, *pfl, *pW1eh, *pW1el, *pW1sh, *pW1sl, *pW2eh, *pW2el, *pW2sh, *pW2sl;
    bf16 *pFb, *pHh, *pHl, *pShh, *pShl;
    { void* t;
      cudaGetSymbolAddress(&t, g_fh);   pfh   = (bf16*)t;
      cudaGetSymbolAddress(&t, g_fl);   pfl   = (bf16*)t;
      cudaGetSymbolAddress(&t, g_W1eh); pW1eh = (bf16*)t;
      cudaGetSymbolAddress(&t, g_W1el); pW1el = (bf16*)t;
      cudaGetSymbolAddress(&t, g_W1sh); pW1sh = (bf16*)t;
      cudaGetSymbolAddress(&t, g_W1sl); pW1sl = (bf16*)t;
      cudaGetSymbolAddress(&t, g_W2eh); pW2eh = (bf16*)t;
      cudaGetSymbolAddress(&t, g_W2el); pW2el = (bf16*)t;
      cudaGetSymbolAddress(&t, g_W2sh); pW2sh = (bf16*)t;
      cudaGetSymbolAddress(&t, g_W2sl); pW2sl = (bf16*)t;
      cudaGetSymbolAddress(&t, g_Fb);   pFb   = (bf16*)t;
      cudaGetSymbolAddress(&t, g_Hh);   pHh   = (bf16*)t;
      cudaGetSymbolAddress(&t, g_Hl);   pHl   = (bf16*)t;
      cudaGetSymbolAddress(&t, g_Shh);  pShh  = (bf16*)t;
      cudaGetSymbolAddress(&t, g_Shl);  pShl  = (bf16*)t;
    }
    int* pDeg; { void* t; cudaGetSymbolAddress(&t, g_deg); pDeg = (int*)t; }

    // ONE side stream + events (same footprint as the passing runs).
    cudaStream_t s1;
    cudaStreamCreateWithFlags(&s1, cudaStreamNonBlocking);
    cudaEvent_t eStart, eSplit, eCsr, eSide, eW;
    cudaEventCreateWithFlags(&eStart, cudaEventDisableTiming);
    cudaEventCreateWithFlags(&eSplit, cudaEventDisableTiming);
    cudaEventCreateWithFlags(&eCsr,   cudaEventDisableTiming);
    cudaEventCreateWithFlags(&eSide,  cudaEventDisableTiming);
    cudaEventCreateWithFlags(&eW,     cudaEventDisableTiming);

    // ---- fork ----
    cudaEventRecord(eStart, 0);
    cudaStreamWaitEvent(s1, eStart, 0);

    // ---- s1: edge-path weight splits (no deps) -> CSR build + type table ----
    tsplit_kernel<<<(IN_DIM * H_E + 255) / 256, 256, 0, s1>>>(W1e + (size_t)IN_DIM * H_E, pW1eh, pW1el, IN_DIM, H_E);
    tsplit_kernel<<<(H_E * OUT_HALF + 255) / 256, 256, 0, s1>>>(W2e, pW2eh, pW2el, H_E, OUT_HALF);
    cudaEventRecord(eW, s1);
    cudaMemsetAsync(pCnt, 0, (size_t)n_nodes * sizeof(int), s1);
    hist_kernel<<<(n_edges + 255) / 256, 256, 0, s1>>>(edge_dst, n_edges);
    {
        const int nb = (n_nodes + 255) / 256;
        scan1_kernel<<<nb, 256, 0, s1>>>(n_nodes);
        scan2_kernel<<<1, 256, 0, s1>>>(nb, n_nodes, n_edges);
        scan3_kernel<<<nb, 256, 0, s1>>>(n_nodes);
    }
    scatter_kernel<<<(n_edges + 255) / 256, 256, 0, s1>>>(edge_src, edge_dst, edge_typ, n_edges);
    type_table_kernel<<<(N_TYPES * H_E + 255) / 256, 256, 0, s1>>>(e_emb, W1e, b1e);
    cudaEventRecord(eCsr, s1);

    // ---- main: feature split -> F-GEMM ----
    {
        const int n4 = n_nodes * IN_DIM / 4;
        split_kernel<<<(n4 + 255) / 256, 256>>>((const float4*)features,
                                                (uint2*)pfh, (uint2*)pfl, n4);
    }
    cudaEventRecord(eSplit, 0);
    cudaStreamWaitEvent(0, eW, 0);

    const int gm = (n_nodes + BM - 1) / BM;

    // F = feat @ W1e_bot  ->  single bf16 [N,512]
    {
        dim3 grid(gm, H_E / BN);
        gemm_bf3<2, false><<<grid, 256, GEMM_SMEM>>>(
            pfh, pfl, pW1eh, pW1el, nullptr, pFb, nullptr,
            n_nodes, IN_DIM, H_E, H_E, nullptr, nullptr, nullptr);
    }

    // ---- s1: self-path GEMMs (gated on eSplit; proven R15 placement) ----
    cudaStreamWaitEvent(s1, eSplit, 0);
    tsplit_kernel<<<(IN_DIM * H_S + 255) / 256, 256, 0, s1>>>(W1s, pW1sh, pW1sl, IN_DIM, H_S);
    tsplit_kernel<<<(H_S * OUT_HALF + 255) / 256, 256, 0, s1>>>(W2s, pW2sh, pW2sl, H_S, OUT_HALF);
    {
        dim3 grid(gm, H_S / BN);
        gemm_bf3<1, true><<<grid, 256, GEMM_SMEM, s1>>>(
            pfh, pfl, pW1sh, pW1sl, nullptr, pShh, pShl,
            n_nodes, IN_DIM, H_S, H_S, b1s, nullptr, nullptr);
    }
    {
        dim3 grid(gm, 1);
        gemm_bf3<0, false><<<grid, 256, GEMM_SMEM, s1>>>(
            pShh, pShl, pW2sh, pW2sl, out, nullptr, nullptr,
            n_nodes, H_S, OUT_HALF, 2 * OUT_HALF, b2s, nullptr, nullptr);
    }
    cudaEventRecord(eSide, s1);

    // ---- main: gather (needs CSR + T) -> W2e-GEMM ----
    cudaStreamWaitEvent(0, eCsr, 0);
    gather_kernel<<<1184, 256>>>(n_nodes);

    // out[:, 128:256] = H @ W2e + deg*b2e
    {
        dim3 grid(gm, 1);
        gemm_bf3<0, false><<<grid, 256, GEMM_SMEM>>>(
            pHh, pHl, pW2eh, pW2el, out + OUT_HALF, nullptr, nullptr,
            n_nodes, H_E, OUT_HALF, 2 * OUT_HALF, nullptr, pDeg, b2e);
    }

    // ---- join ----
    cudaStreamWaitEvent(0, eSide, 0);
}